// round 12
// baseline (speedup 1.0000x reference)
#include <cuda_runtime.h>

#define H 2048
#define W 2048
#define BW 32
#define BH 64
#define RPT 8             // output rows per thread
#define TROWS (BH + 6)    // 70 horizontal-sum rows per block
#define NTASK (TROWS * 8) // 560 4-wide h-pass tasks

__global__ __launch_bounds__(256)
void plane_fit_kernel(const float* __restrict__ x, float* __restrict__ out) {
    // Interleaved horizontal sums: .x = 7-tap box, .y = 7-tap ramp
    __shared__ float2 hbr[TROWS][BW];

    const int tx = threadIdx.x;          // 0..31 (lane)
    const int ty = threadIdx.y;          // 0..7
    const int tid = ty * 32 + tx;
    const int bx = blockIdx.x * BW;
    const int by = blockIdx.y * BH;

    const bool x_interior = (bx != 0) && (bx != W - BW);
    const bool y_interior = (by != 0) && (by != H - BH);

    if (x_interior) {
        // ---- Stage 1: 560 tasks. Rounds 1-2 (tasks 0..511 = rows 0..63) by
        //      all threads; round 3 (tasks 512..559 = rows 64..69, needed
        //      ONLY by warp 7's vertical pass) deferred past the main barrier.
        //      All loads batched up front (MLP up to 9). ----
        auto taskaddr = [&](int t) {
            int r = t >> 3;
            int gi = by + r - 3;
            if (!y_interior) gi = gi < 0 ? 0 : (gi > H - 1 ? H - 1 : gi);
            return reinterpret_cast<const float4*>(
                x + (size_t)gi * W + (bx + (t & 7) * 4 - 4));   // 16B-aligned
        };
        auto compute_store = [&](int t, float4 A, float4 B, float4 C) {
            float v1 = A.y, v2 = A.z, v3 = A.w;
            float v4 = B.x, v5 = B.y, v6 = B.z, v7 = B.w;
            float v8 = C.x, v9 = C.y, v10 = C.z;

            float s0 = ((v1 + v2) + (v3 + v4)) + ((v5 + v6) + v7);
            float s1 = s0 - v1 + v8;
            float s2 = s1 - v2 + v9;
            float s3 = s2 - v3 + v10;

            float r0 = fmaf(3.f, v7 - v1, fmaf(2.f, v6 - v2, v5 - v3));
            float r1 = fmaf(3.f, v8 - v2, fmaf(2.f, v7 - v3, v6 - v4));
            float r2 = fmaf(3.f, v9 - v3, fmaf(2.f, v8 - v4, v7 - v5));
            float r3 = fmaf(3.f, v10 - v4, fmaf(2.f, v9 - v5, v8 - v6));

            float4* dst = reinterpret_cast<float4*>(&hbr[t >> 3][(t & 7) * 4]);
            dst[0] = make_float4(s0, r0, s1, r1);
            dst[1] = make_float4(s2, r2, s3, r3);
        };

        const bool has3 = (tid < NTASK - 512);           // 48 threads
        const float4* p0 = taskaddr(tid);
        const float4* p1 = taskaddr(tid + 256);
        const float4* p2 = has3 ? taskaddr(tid + 512) : p0;  // safe fallback
        // Batch all loads before any compute
        float4 A0 = p0[0], B0 = p0[1], C0 = p0[2];
        float4 A1 = p1[0], B1 = p1[1], C1 = p1[2];
        float4 A2 = p2[0], B2 = p2[1], C2 = p2[2];
        compute_store(tid,       A0, B0, C0);
        compute_store(tid + 256, A1, B1, C1);
        __syncthreads();                     // rows 0..63 published

        // Round 3: warps 0,1 finish rows 64..69; warp 7 (their only consumer)
        // waits on named barrier 1 (96 threads = warps 0,1,7). Warps 2..6
        // proceed straight to the vertical pass.
        if (tid < 64) {
            if (has3) compute_store(tid + 512, A2, B2, C2);
            asm volatile("bar.sync 1, 96;" ::: "memory");
        } else if (tid >= 224) {
            asm volatile("bar.sync 1, 96;" ::: "memory");
        }
    } else {
        // ---- x-edge blocks (64 of 2048): scalar path with full clamping ----
        #pragma unroll 1
        for (int t = tid; t < TROWS * BW; t += 256) {
            int r = t >> 5;
            int c = t & 31;
            int gi = by + r - 3;
            gi = gi < 0 ? 0 : (gi > H - 1 ? H - 1 : gi);
            const float* row = x + (size_t)gi * W;
            float s = 0.f, rmp = 0.f;
            #pragma unroll
            for (int d = 0; d < 7; d++) {
                int gj = bx + c + d - 3;
                gj = gj < 0 ? 0 : (gj > W - 1 ? W - 1 : gj);
                float v = row[gj];
                s += v;
                rmp += (float)(d - 3) * v;
            }
            hbr[r][c] = make_float2(s, rmp);
        }
        __syncthreads();
    }

    // ---- Permuted column ownership (3-shuffle store transpose) ----
    // Writer lane l (<24) stores the float4 at byte offset 16*l of the 384B
    // output row segment; it needs pixels sA=4q+m and sA+1 (q=l/3, m=l%3).
    // Lane l<24 owns column sA; lanes 24..31 own leftover columns 4k+3.
    // Neighbor owner: lane l+1 (m=0,1) or lane 24+q (m=2): ONE shuffle source.
    const int q = tx / 3;
    const int m = tx - 3 * q;
    const int col = (tx < 24) ? (4 * q + m) : (4 * (tx - 24) + 3);
    const int nbr = (tx < 24) ? ((m == 2) ? (24 + q) : (tx + 1)) : 0;
    const bool writer = (tx < 24);

    // ---- Vertical pass: sliding 7-row window on owned column ----
    const int r0 = ty * RPT;
    float2 w[7];
    #pragma unroll
    for (int k = 0; k < 7; k++) w[k] = hbr[r0 + k][col];

    float sb = 0.f, sbr = 0.f, srb = 0.f;
    #pragma unroll
    for (int k = 0; k < 7; k++) {
        sb  += w[k].x;
        sbr += w[k].y;
        srb += (float)(k - 3) * w[k].x;
    }

    const float inv196 = 1.0f / 196.0f;
    const float inv49  = 1.0f / 49.0f;
    float* const rowbase = out + ((size_t)(by + r0) * W + bx) * 3 + tx * 4;

    #pragma unroll
    for (int i = 0; i < RPT; i++) {
        float c0 = sbr * inv196;   // horizontal-ramp, vertical-box
        float c1 = srb * inv196;   // horizontal-box, vertical-ramp
        float c2 = sb  * inv49;    // mean

        float n0 = __shfl_sync(0xffffffffu, c0, nbr);
        float n1 = __shfl_sync(0xffffffffu, c1, nbr);
        float n2 = __shfl_sync(0xffffffffu, c2, nbr);

        //   m=0: [c0 c1 c2 n0]   m=1: [c1 c2 n0 n1]   m=2: [c2 n0 n1 n2]
        float w0 = (m == 0) ? c0 : ((m == 1) ? c1 : c2);
        float w1 = (m == 0) ? c1 : ((m == 1) ? c2 : n0);
        float w2 = (m == 0) ? c2 : ((m == 1) ? n0 : n1);
        float w3 = (m == 0) ? n0 : ((m == 1) ? n1 : n2);

        if (writer) {
            __stcs(reinterpret_cast<float4*>(rowbase + (size_t)i * W * 3),
                   make_float4(w0, w1, w2, w3));
        }

        if (i < RPT - 1) {
            float2 nw = hbr[r0 + 7 + i][col];   // one fresh row from smem
            float2 ow = w[i];                   // static index after unroll
            srb = srb - sb + fmaf(4.f, ow.x, 3.f * nw.x);
            sb  = sb + (nw.x - ow.x);
            sbr = sbr + (nw.y - ow.y);
            w[i] = nw;
        }
    }
}

extern "C" void kernel_launch(void* const* d_in, const int* in_sizes, int n_in,
                              void* d_out, int out_size) {
    const float* x = (const float*)d_in[0];
    float* out = (float*)d_out;
    dim3 block(32, 8);
    dim3 grid(W / BW, H / BH);   // 64 x 32 = 2048 blocks
    plane_fit_kernel<<<grid, block>>>(x, out);
}

// round 13
// speedup vs baseline: 1.1052x; 1.1052x over previous
#include <cuda_runtime.h>

#define H 2048
#define W 2048
#define BW 32
#define BH 64
#define RPT 8             // output rows per thread
#define TROWS (BH + 6)    // 70 horizontal-sum rows per block
#define NTASK (TROWS * 8) // 560 4-wide h-pass tasks

__global__ __launch_bounds__(256)
void plane_fit_kernel(const float* __restrict__ x, float* __restrict__ out) {
    // Split horizontal-sum planes: box and ramp as separate float arrays so
    // the permuted-column vertical loads are conflict-free LDS.32.
    __shared__ float hbox[TROWS][BW];
    __shared__ float hramp[TROWS][BW];

    const int tx = threadIdx.x;          // 0..31 (lane)
    const int ty = threadIdx.y;          // 0..7
    const int tid = ty * 32 + tx;
    const int bx = blockIdx.x * BW;
    const int by = blockIdx.y * BH;

    const bool x_interior = (bx != 0) && (bx != W - BW);
    const bool y_interior = (by != 0) && (by != H - BH);

    if (x_interior) {
        // ---- Stage 1: 560 tasks, 2 per thread with batched loads (MLP=6),
        //      plus a 48-thread remainder. Task t: r = t>>3, cg = t&7. ----
        auto taskaddr = [&](int t) {
            int r = t >> 3;
            int gi = by + r - 3;
            if (!y_interior) gi = gi < 0 ? 0 : (gi > H - 1 ? H - 1 : gi);
            return reinterpret_cast<const float4*>(
                x + (size_t)gi * W + (bx + (t & 7) * 4 - 4));   // 16B-aligned
        };
        auto compute_store = [&](int t, float4 A, float4 B, float4 C) {
            float v1 = A.y, v2 = A.z, v3 = A.w;
            float v4 = B.x, v5 = B.y, v6 = B.z, v7 = B.w;
            float v8 = C.x, v9 = C.y, v10 = C.z;

            float s0 = ((v1 + v2) + (v3 + v4)) + ((v5 + v6) + v7);
            float s1 = s0 - v1 + v8;
            float s2 = s1 - v2 + v9;
            float s3 = s2 - v3 + v10;

            float r0 = fmaf(3.f, v7 - v1, fmaf(2.f, v6 - v2, v5 - v3));
            float r1 = fmaf(3.f, v8 - v2, fmaf(2.f, v7 - v3, v6 - v4));
            float r2 = fmaf(3.f, v9 - v3, fmaf(2.f, v8 - v4, v7 - v5));
            float r3 = fmaf(3.f, v10 - v4, fmaf(2.f, v9 - v5, v8 - v6));

            int r = t >> 3, c4 = (t & 7) * 4;
            *reinterpret_cast<float4*>(&hbox[r][c4])  = make_float4(s0, s1, s2, s3);
            *reinterpret_cast<float4*>(&hramp[r][c4]) = make_float4(r0, r1, r2, r3);
        };

        const float4* p0 = taskaddr(tid);
        const float4* p1 = taskaddr(tid + 256);
        // Batch all six loads before any compute (MLP=6)
        float4 A0 = p0[0], B0 = p0[1], C0 = p0[2];
        float4 A1 = p1[0], B1 = p1[1], C1 = p1[2];
        compute_store(tid,       A0, B0, C0);
        compute_store(tid + 256, A1, B1, C1);
        if (tid < NTASK - 512) {
            const float4* p2 = taskaddr(tid + 512);
            float4 A2 = p2[0], B2 = p2[1], C2 = p2[2];
            compute_store(tid + 512, A2, B2, C2);
        }
    } else {
        // ---- x-edge blocks (64 of 2048): scalar path with full clamping ----
        #pragma unroll 1
        for (int t = tid; t < TROWS * BW; t += 256) {
            int r = t >> 5;
            int c = t & 31;
            int gi = by + r - 3;
            gi = gi < 0 ? 0 : (gi > H - 1 ? H - 1 : gi);
            const float* row = x + (size_t)gi * W;
            float s = 0.f, rmp = 0.f;
            #pragma unroll
            for (int d = 0; d < 7; d++) {
                int gj = bx + c + d - 3;
                gj = gj < 0 ? 0 : (gj > W - 1 ? W - 1 : gj);
                float v = row[gj];
                s += v;
                rmp += (float)(d - 3) * v;
            }
            hbox[r][c] = s;
            hramp[r][c] = rmp;
        }
    }
    __syncthreads();

    // ---- Permuted column ownership (3-shuffle store transpose) ----
    // Writer lane l (<24) stores the float4 at byte offset 16*l of the 384B
    // output row segment; it needs pixels sA=4q+m and sA+1 (q=l/3, m=l%3).
    // Lane l<24 owns column sA; lanes 24..31 own leftover columns 4k+3.
    // Neighbor owner: lane l+1 (m=0,1) or lane 24+q (m=2): ONE shuffle source.
    const int q = tx / 3;
    const int m = tx - 3 * q;
    const int col = (tx < 24) ? (4 * q + m) : (4 * (tx - 24) + 3);
    const int nbr = (tx < 24) ? ((m == 2) ? (24 + q) : (tx + 1)) : 0;
    const bool writer = (tx < 24);

    // ---- Vertical pass: sliding 7-row window, conflict-free LDS.32 ----
    const int r0 = ty * RPT;
    float wb[7], wr[7];
    #pragma unroll
    for (int k = 0; k < 7; k++) {
        wb[k] = hbox[r0 + k][col];
        wr[k] = hramp[r0 + k][col];
    }

    float sb = 0.f, sbr = 0.f, srb = 0.f;
    #pragma unroll
    for (int k = 0; k < 7; k++) {
        sb  += wb[k];
        sbr += wr[k];
        srb += (float)(k - 3) * wb[k];
    }

    const float inv196 = 1.0f / 196.0f;
    const float inv49  = 1.0f / 49.0f;
    float* const rowbase = out + ((size_t)(by + r0) * W + bx) * 3 + tx * 4;

    #pragma unroll
    for (int i = 0; i < RPT; i++) {
        float c0 = sbr * inv196;   // horizontal-ramp, vertical-box
        float c1 = srb * inv196;   // horizontal-box, vertical-ramp
        float c2 = sb  * inv49;    // mean

        float n0 = __shfl_sync(0xffffffffu, c0, nbr);
        float n1 = __shfl_sync(0xffffffffu, c1, nbr);
        float n2 = __shfl_sync(0xffffffffu, c2, nbr);

        //   m=0: [c0 c1 c2 n0]   m=1: [c1 c2 n0 n1]   m=2: [c2 n0 n1 n2]
        float w0 = (m == 0) ? c0 : ((m == 1) ? c1 : c2);
        float w1 = (m == 0) ? c1 : ((m == 1) ? c2 : n0);
        float w2 = (m == 0) ? c2 : ((m == 1) ? n0 : n1);
        float w3 = (m == 0) ? n0 : ((m == 1) ? n1 : n2);

        if (writer) {
            __stcs(reinterpret_cast<float4*>(rowbase + (size_t)i * W * 3),
                   make_float4(w0, w1, w2, w3));
        }

        if (i < RPT - 1) {
            float nb = hbox[r0 + 7 + i][col];    // fresh rows, conflict-free
            float nr = hramp[r0 + 7 + i][col];
            float ob = wb[i];                    // static index after unroll
            srb = srb - sb + fmaf(4.f, ob, 3.f * nb);
            sb  = sb + (nb - ob);
            sbr = sbr + (nr - wr[i]);
            wb[i] = nb;
            wr[i] = nr;
        }
    }
}

extern "C" void kernel_launch(void* const* d_in, const int* in_sizes, int n_in,
                              void* d_out, int out_size) {
    const float* x = (const float*)d_in[0];
    float* out = (float*)d_out;
    dim3 block(32, 8);
    dim3 grid(W / BW, H / BH);   // 64 x 32 = 2048 blocks
    plane_fit_kernel<<<grid, block>>>(x, out);
}